// round 15
// baseline (speedup 1.0000x reference)
#include <cuda_runtime.h>
#include <cuda_bf16.h>
#include <math.h>
#include <stdint.h>

#define BATCH 1024
#define KNN   16
#define H     256
#define G     2000
#define D     4000          // 2*G
#define NROWS (2*BATCH*KNN) // 32768

typedef __nv_bfloat16 bf16;

// ---------------- scratch (static device arrays; no allocation) --------------
__device__ bf16  g_aggb[(size_t)2 * BATCH * D];      // bf16 agg, 16MB
__device__ float g_part[(size_t)4 * 4 * BATCH * H]; // split-K partials, 16MB
__device__ float g_h2[(size_t)2 * BATCH * H];
__device__ bf16  g_wt[4][(size_t)H * D];             // W^T bf16: [n][k], 8MB

// ----------------------------- PTX helpers ----------------------------------
__device__ __forceinline__ uint32_t smem_u32(const void* p) {
    uint32_t a;
    asm("{ .reg .u64 tmp; cvta.to.shared.u64 tmp, %1; cvt.u32.u64 %0, tmp; }"
        : "=r"(a) : "l"(p));
    return a;
}

__device__ __forceinline__ void mma_bf16(float& c0, float& c1, float& c2, float& c3,
                                         uint32_t a0, uint32_t a1, uint32_t a2, uint32_t a3,
                                         uint32_t b0, uint32_t b1) {
    asm volatile(
        "mma.sync.aligned.m16n8k16.row.col.f32.bf16.bf16.f32 "
        "{%0,%1,%2,%3}, {%4,%5,%6,%7}, {%8,%9}, {%0,%1,%2,%3};\n"
        : "+f"(c0), "+f"(c1), "+f"(c2), "+f"(c3)
        : "r"(a0), "r"(a1), "r"(a2), "r"(a3), "r"(b0), "r"(b1));
}

__device__ __forceinline__ void ldsm_x4(uint32_t* r, uint32_t addr) {
    asm volatile("ldmatrix.sync.aligned.m8n8.x4.shared.b16 {%0,%1,%2,%3}, [%4];"
                 : "=r"(r[0]), "=r"(r[1]), "=r"(r[2]), "=r"(r[3]) : "r"(addr));
}

__device__ __forceinline__ void sts128(uint32_t addr, uint32_t a, uint32_t b,
                                       uint32_t c, uint32_t d) {
    asm volatile("st.shared.v4.b32 [%0], {%1,%2,%3,%4};"
                 :: "r"(addr), "r"(a), "r"(b), "r"(c), "r"(d));
}

__device__ __forceinline__ void cp_async16_s(uint32_t saddr, const void* gsrc) {
    asm volatile("cp.async.ca.shared.global [%0], [%1], 16;\n" :: "r"(saddr), "l"(gsrc));
}
__device__ __forceinline__ void cp_async_commit() { asm volatile("cp.async.commit_group;\n"); }
__device__ __forceinline__ void cp_async_wait0()  { asm volatile("cp.async.wait_group 0;\n"); }

__device__ __forceinline__ uint32_t pack2(float x, float y) {
    __nv_bfloat162 h = __floats2bfloat162_rn(x, y);
    return *reinterpret_cast<uint32_t*>(&h);
}

__device__ __forceinline__ float tanh_fast(float x) {
    float e = __expf(2.f * x);
    return 1.f - __fdividef(2.f, e + 1.f);
}

// =============================================================================
// Kernel 0: convert + transpose weights to bf16 W^T[n][k] (k contiguous).
// =============================================================================
__global__ void k_cvt(const float* __restrict__ Wa1, const float* __restrict__ W1,
                      const float* __restrict__ Wd, const float* __restrict__ Wr)
{
    __shared__ float tile[32][33];
    const float* src = (blockIdx.z == 0) ? Wa1 : (blockIdx.z == 1) ? W1
                     : (blockIdx.z == 2) ? Wd : Wr;
    bf16* dst = g_wt[blockIdx.z];
    int k0 = blockIdx.x * 32, n0 = blockIdx.y * 32;
    int tx = threadIdx.x, ty = threadIdx.y;
#pragma unroll
    for (int i = 0; i < 4; i++)
        tile[ty + 8 * i][tx] = src[(size_t)(k0 + ty + 8 * i) * H + n0 + tx];
    __syncthreads();
#pragma unroll
    for (int i = 0; i < 4; i++)
        dst[(size_t)(n0 + ty + 8 * i) * D + k0 + tx] = __float2bfloat16(tile[tx][ty + 8 * i]);
}

// =============================================================================
// Kernel 1 (bf16 mma + ldmatrix): attention logits + FUSED weights/aggregation.
// Block 128x256, KT=64, 1024 thr, 32 warps (8m x 4n), warp tile 16x64.
// 32 warps/SM for gather-latency hiding; acc = 32 regs/thread.
// =============================================================================
#define L_BM 128
#define L_NSTG 63
#define L_AB 16384
#define L_BB 32768
#define L_SMEM (2*L_AB + 2*L_BB)

__global__ __launch_bounds__(1024, 1) void k_logits_fused(
    const int* __restrict__ idx1, const int* __restrict__ idx2,
    const float* __restrict__ nw1, const float* __restrict__ nw2,
    const float* __restrict__ sp, const float* __restrict__ un,
    const float* __restrict__ ba1, const float* __restrict__ Wa2,
    const float* __restrict__ ba2)
{
    extern __shared__ __align__(1024) char sm[];
    __shared__ int   rid[L_BM];
    __shared__ float psum[4 * L_BM];
    __shared__ float s_ba1[256], s_wa2[256];
    __shared__ float s_lgt[L_BM];
    __shared__ float s_w[L_BM];

    const int t    = threadIdx.x;
    const int lane = t & 31;
    const int wid  = t >> 5;
    const int wm   = wid & 7;          // rows wm*16
    const int wn   = wid >> 3;         // cols wn*64
    const int g    = lane >> 2;
    const int tig  = lane & 3;
    const int row0 = blockIdx.x * L_BM;
    const int gb0  = blockIdx.x * 8;
    const uint32_t smb = smem_u32(sm);

    if (t < L_BM) {
        int r = row0 + t;
        rid[t] = (r < BATCH * KNN) ? idx1[r] : idx2[r - BATCH * KNN];
    }
    if (t < 256) { s_ba1[t] = ba1[t]; s_wa2[t] = Wa2[t]; }
    __syncthreads();

    // ---- A producer: 8 threads/row, 8 floats each ----
    const int arow  = t >> 3;          // 0..127
    const int agrp8 = t & 7;           // cols agrp8*8..+7
    const size_t abase = (size_t)rid[arow] * G;
    const uint32_t ast = smb + arow * 128
                       + (((uint32_t)agrp8 * 16) ^ ((uint32_t)(arow & 7) << 4));

    // ---- consumer (ldmatrix) mappings: warp tile 16x64 ----
    const int ar_lo = (lane & 7) + ((lane >> 3) & 1) * 8;
    const int akh   = (lane >> 4) & 1;
    const uint32_t ac_base = smb + (wm * 16 + ar_lo) * 128;
    const uint32_t acx = (uint32_t)(ar_lo & 7) << 4;
    const int nr_lo = (lane & 7) + ((lane >> 4) & 1) * 8;
    const int bkh   = (lane >> 3) & 1;
    const uint32_t bc_base = smb + 2 * L_AB + (wn * 64 + nr_lo) * 128;
    const uint32_t bcx = (uint32_t)(nr_lo & 7) << 4;

    const bf16* WT0 = g_wt[0];

    float acc[8][4];
#pragma unroll
    for (int nt = 0; nt < 8; nt++)
#pragma unroll
        for (int j = 0; j < 4; j++) acc[nt][j] = 0.f;

    // ---- prologue: stage 0 (cols < 64, all spliced, valid) ----
    {
        const float* s0 = sp + abase + agrp8 * 8;
        float4 v0 = *reinterpret_cast<const float4*>(s0);
        float4 v1 = *reinterpret_cast<const float4*>(s0 + 4);
        sts128(ast, pack2(__logf(v0.x + 0.01f), __logf(v0.y + 0.01f)),
                    pack2(__logf(v0.z + 0.01f), __logf(v0.w + 0.01f)),
                    pack2(__logf(v1.x + 0.01f), __logf(v1.y + 0.01f)),
                    pack2(__logf(v1.z + 0.01f), __logf(v1.w + 0.01f)));
#pragma unroll
        for (int i = 0; i < 2; i++) {
            int p = t + i * 1024;
            int br = p >> 3, bc = p & 7;
            uint32_t d = smb + 2 * L_AB + br * 128
                       + (((uint32_t)bc * 16) ^ ((uint32_t)(br & 7) << 4));
            cp_async16_s(d, WT0 + (size_t)br * D + bc * 8);
        }
        cp_async_commit();
        cp_async_wait0();
        __syncthreads();
    }

    int buf = 0;
#pragma unroll 1
    for (int s = 0; s < L_NSTG; s++) {
        const bool nx = (s + 1) < L_NSTG;
        float4 v0, v1;
        bool vn = false;
        if (nx) {
            int c = (s + 1) * 64 + agrp8 * 8;
            vn = (c < D);
            if (vn) {
                const float* sc = (c < G) ? (sp + abase + c) : (un + abase + (c - G));
                v0 = *reinterpret_cast<const float4*>(sc);
                v1 = *reinterpret_cast<const float4*>(sc + 4);
            }
            const uint32_t bo = (uint32_t)(buf ^ 1) * L_BB;
            const int kb = (s + 1) * 64;
#pragma unroll
            for (int i = 0; i < 2; i++) {
                int p = t + i * 1024;
                int br = p >> 3, bc = p & 7;
                uint32_t d = smb + 2 * L_AB + bo + br * 128
                           + (((uint32_t)bc * 16) ^ ((uint32_t)(br & 7) << 4));
                int kk = kb + bc * 8;
                if (kk + 8 <= D) cp_async16_s(d, WT0 + (size_t)br * D + kk);
                else             sts128(d, 0, 0, 0, 0);
            }
            cp_async_commit();
        }

        // ---- mma on current buffer ----
        const uint32_t Ab = (uint32_t)buf * L_AB;
        const uint32_t Bb = (uint32_t)buf * L_BB;
#pragma unroll
        for (int ks = 0; ks < 4; ks++) {
            uint32_t a0[4];
            const uint32_t au = (((uint32_t)(ks * 2 + akh)) * 16) ^ acx;
            ldsm_x4(a0, ac_base + Ab + au);
            const uint32_t bu = (((uint32_t)(ks * 2 + bkh)) * 16) ^ bcx;
#pragma unroll
            for (int ntp = 0; ntp < 4; ntp++) {
                uint32_t b[4];
                ldsm_x4(b, bc_base + Bb + ntp * 2048 + bu);
                mma_bf16(acc[2*ntp][0], acc[2*ntp][1], acc[2*ntp][2], acc[2*ntp][3],
                         a0[0], a0[1], a0[2], a0[3], b[0], b[1]);
                mma_bf16(acc[2*ntp+1][0], acc[2*ntp+1][1], acc[2*ntp+1][2], acc[2*ntp+1][3],
                         a0[0], a0[1], a0[2], a0[3], b[2], b[3]);
            }
        }

        if (nx) {
            const uint32_t ao = (uint32_t)(buf ^ 1) * L_AB;
            if (vn) {
                sts128(ast + ao, pack2(__logf(v0.x + 0.01f), __logf(v0.y + 0.01f)),
                                 pack2(__logf(v0.z + 0.01f), __logf(v0.w + 0.01f)),
                                 pack2(__logf(v1.x + 0.01f), __logf(v1.y + 0.01f)),
                                 pack2(__logf(v1.z + 0.01f), __logf(v1.w + 0.01f)));
            } else {
                sts128(ast + ao, 0, 0, 0, 0);
            }
        }
        cp_async_wait0();
        __syncthreads();
        buf ^= 1;
    }

    // ---------- logits epilogue: fast tanh + dot(Wa2), hierarchical reduce ----
    float bb[8][2], ww[8][2];
#pragma unroll
    for (int nt = 0; nt < 8; nt++) {
        int col = wn * 64 + nt * 8 + tig * 2;
        bb[nt][0] = s_ba1[col];  bb[nt][1] = s_ba1[col + 1];
        ww[nt][0] = s_wa2[col];  ww[nt][1] = s_wa2[col + 1];
    }
    {
        float slo = 0.f, shi = 0.f;
#pragma unroll
        for (int nt = 0; nt < 8; nt++) {
            slo += tanh_fast(acc[nt][0] + bb[nt][0]) * ww[nt][0];
            slo += tanh_fast(acc[nt][1] + bb[nt][1]) * ww[nt][1];
            shi += tanh_fast(acc[nt][2] + bb[nt][0]) * ww[nt][0];
            shi += tanh_fast(acc[nt][3] + bb[nt][1]) * ww[nt][1];
        }
        slo += __shfl_xor_sync(0xffffffffu, slo, 1);
        slo += __shfl_xor_sync(0xffffffffu, slo, 2);
        shi += __shfl_xor_sync(0xffffffffu, shi, 1);
        shi += __shfl_xor_sync(0xffffffffu, shi, 2);
        if (tig == 0) {
            psum[wn * L_BM + wm * 16 + g]     = slo;
            psum[wn * L_BM + wm * 16 + g + 8] = shi;
        }
    }
    __syncthreads();
    if (t < L_BM) {
        float s = psum[t] + psum[L_BM + t] + psum[2 * L_BM + t] + psum[3 * L_BM + t];
        s_lgt[t] = s + __ldg(&ba2[0]);
    }
    __syncthreads();

    // ---------- fused weights: softmax over 16 logits + nw fold, per group ----
    if (t < 8) {
        int gb = gb0 + t;
        const float* nwp = (gb < BATCH) ? (nw1 + (size_t)gb * KNN)
                                        : (nw2 + (size_t)(gb - BATCH) * KNN);
        float l[KNN];
        float m = -1e30f;
#pragma unroll
        for (int k = 0; k < KNN; k++) { l[k] = s_lgt[t * KNN + k]; m = fmaxf(m, l[k]); }
        float ssum = 0.f;
#pragma unroll
        for (int k = 0; k < KNN; k++) { l[k] = __expf(l[k] - m); ssum += l[k]; }
        float inv_s = 1.f / ssum;
        float tsum = 0.f;
#pragma unroll
        for (int k = 0; k < KNN; k++) { l[k] = nwp[k] * l[k] * inv_s; tsum += l[k]; }
        float inv = 1.f / (tsum + 1e-12f);
#pragma unroll
        for (int k = 0; k < KNN; k++) s_w[t * KNN + k] = l[k] * inv;
    }
    __syncthreads();

    // ---------- fused aggregation: 8 groups x 500 col-chunks of 8 ----
#pragma unroll 1
    for (int task = t; task < 4000; task += 1024) {
        int grp = task / 500;
        int ch  = task - grp * 500;
        int c   = ch * 8;
        const float* base = (c < G) ? sp : un;
        int cc = (c < G) ? c : c - G;
        const int*   idp = rid + grp * KNN;
        const float* wp  = s_w + grp * KNN;
        float a[8];
#pragma unroll
        for (int j = 0; j < 8; j++) a[j] = 0.f;
#pragma unroll
        for (int k = 0; k < KNN; k++) {
            const float* rp = base + (size_t)idp[k] * G + cc;
            float4 v0 = *reinterpret_cast<const float4*>(rp);
            float4 v1 = *reinterpret_cast<const float4*>(rp + 4);
            float wk = wp[k];
            a[0] = fmaf(wk, __logf(v0.x + 0.01f), a[0]);
            a[1] = fmaf(wk, __logf(v0.y + 0.01f), a[1]);
            a[2] = fmaf(wk, __logf(v0.z + 0.01f), a[2]);
            a[3] = fmaf(wk, __logf(v0.w + 0.01f), a[3]);
            a[4] = fmaf(wk, __logf(v1.x + 0.01f), a[4]);
            a[5] = fmaf(wk, __logf(v1.y + 0.01f), a[5]);
            a[6] = fmaf(wk, __logf(v1.z + 0.01f), a[6]);
            a[7] = fmaf(wk, __logf(v1.w + 0.01f), a[7]);
        }
        uint4 pk;
        pk.x = pack2(a[0], a[1]); pk.y = pack2(a[2], a[3]);
        pk.z = pack2(a[4], a[5]); pk.w = pack2(a[6], a[7]);
        *reinterpret_cast<uint4*>(&g_aggb[(size_t)(gb0 + grp) * D + c]) = pk;
    }
}

// =============================================================================
// Kernel 4 (bf16 mma + ldmatrix + split-K x4): four fused GEMMs, virtual M=4096.
// Block 64x128xK1000, grid (64, 2, 4) = 512 CTAs. Partials -> g_part.
// =============================================================================
#define Q_AB 8192
#define Q_BB 16384
#define Q_SMEM (2*Q_AB + 2*Q_BB)
#define Q_KSPLIT 1000
#define Q_NSTG 16            // ceil(1000/64)

__global__ __launch_bounds__(256, 3) void k_gemm4_v3(
    const float* __restrict__ enc)
{
    extern __shared__ __align__(1024) char sm[];

    const int t    = threadIdx.x;
    const int lane = t & 31;
    const int wid  = t >> 5;
    const int wm   = wid & 3;
    const int wn   = wid >> 2;
    const int g    = lane >> 2;
    const int tig  = lane & 3;
    const int nb   = blockIdx.y;
    const int vm0  = blockIdx.x * 64;
    const int src  = vm0 >> 10;
    const int kz   = blockIdx.z;
    const int kbase = kz * Q_KSPLIT;
    const int kend  = kbase + Q_KSPLIT;
    const uint32_t smb = smem_u32(sm);

    const bf16* WT = (src < 2) ? g_wt[1] : (src == 2 ? g_wt[2] : g_wt[3]);

    const int arow = t >> 2;
    const int agrp = t & 3;
    const int brow = (vm0 & 1023) + arow;
    const bf16*  abf = nullptr;
    const float* aef = nullptr;
    if      (src == 0) abf = g_aggb + (size_t)brow * D;
    else if (src == 1) abf = g_aggb + (size_t)(BATCH + brow) * D;
    else if (src == 2) { abf = g_aggb + (size_t)brow * D; aef = enc + (size_t)brow * D; }
    else               aef = enc + (size_t)brow * D;

    const uint32_t axor = (uint32_t)(arow & 7) << 4;
    const uint32_t ast0 = smb + arow * 128 + (((uint32_t)agrp * 32) ^ axor);
    const uint32_t ast1 = smb + arow * 128 + (((uint32_t)agrp * 32 + 16) ^ axor);

    uint32_t bst[4]; const bf16* bsrc[4]; int bko[4];
#pragma unroll
    for (int i = 0; i < 4; i++) {
        int p = t + i * 256;
        int brr = p >> 3, bc = p & 7;
        bst[i]  = smb + 2 * Q_AB + brr * 128 + (((uint32_t)bc * 16) ^ ((uint32_t)(brr & 7) << 4));
        bsrc[i] = WT + (size_t)(nb * 128 + brr) * D;
        bko[i]  = bc * 8;
    }

    const int ar_lo = (lane & 7) + ((lane >> 3) & 1) * 8;
    const int akh   = (lane >> 4) & 1;
    const uint32_t ac_base = smb + (wm * 16 + ar_lo) * 128;
    const uint32_t acx = (uint32_t)(ar_lo & 7) << 4;
    const int nr_lo = (lane & 7) + ((lane >> 4) & 1) * 8;
    const int bkh   = (lane >> 3) & 1;
    const uint32_t bc_base = smb + 2 * Q_AB + (wn * 64 + nr_lo) * 128;
    const uint32_t bcx = (uint32_t)(nr_lo & 7) << 4;

    float acc[8][4];
#pragma unroll
    for (int nt = 0; nt < 8; nt++)
#pragma unroll
        for (int j = 0; j < 4; j++) acc[nt][j] = 0.f;

    auto produce_A = [&](int kb0, uint32_t ao) {
        int c = kb0 + agrp * 16;
        bool h0 = (c + 8 <= kend), h1 = (c + 16 <= kend);
        if (src < 2) {
            if (h0) cp_async16_s(ast0 + ao, abf + c);
            else    sts128(ast0 + ao, 0, 0, 0, 0);
            if (h1) cp_async16_s(ast1 + ao, abf + c + 8);
            else    sts128(ast1 + ao, 0, 0, 0, 0);
        } else if (src == 2) {
            if (h0) {
                uint4 ab0 = *reinterpret_cast<const uint4*>(abf + c);
                float4 e0 = *reinterpret_cast<const float4*>(aef + c);
                float4 e1 = *reinterpret_cast<const float4*>(aef + c + 4);
                __nv_bfloat162* al = reinterpret_cast<__nv_bfloat162*>(&ab0);
                float2 f0 = __bfloat1622float2(al[0]);
                float2 f1 = __bfloat1622float2(al[1]);
                float2 f2 = __bfloat1622float2(al[2]);
                float2 f3 = __bfloat1622float2(al[3]);
                sts128(ast0 + ao,
                       pack2(f0.x - e0.x, f0.y - e0.y), pack2(f1.x - e0.z, f1.y - e0.w),
                       pack2(f2.x - e1.x, f2.y - e1.y), pack2(f3.x - e1.z, f3.y - e1.w));
            } else sts128(ast0 + ao, 0, 0, 0, 0);
            if (h1) {
                uint4 ab1 = *reinterpret_cast<const uint4*>(abf + c + 8);
                float4 e2 = *reinterpret_cast<const float4*>(aef + c + 8);
                float4 e3 = *reinterpret_cast<const float4*>(aef + c + 12);
                __nv_bfloat162* ah = reinterpret_cast<__nv_bfloat162*>(&ab1);
                float2 f4 = __bfloat1622float2(ah[0]);
                float2 f5 = __bfloat1622float2(ah[1]);
                float2 f6 = __bfloat1622float2(ah[2]);
                float2 f7 = __bfloat1622float2(ah[3]);
                sts128(ast1 + ao,
                       pack2(f4.x - e2.x, f4.y - e2.y), pack2(f5.x - e2.z, f5.y - e2.w),
                       pack2(f6.x - e3.x, f6.y - e3.y), pack2(f7.x - e3.z, f7.y - e3.w));
            } else sts128(ast1 + ao, 0, 0, 0, 0);
        } else {
            if (h0) {
                const float* sc = aef + c;
                float4 v0 = *reinterpret_cast<const float4*>(sc);
                float4 v1 = *reinterpret_cast<const float4*>(sc + 4);
                sts128(ast0 + ao, pack2(v0.x, v0.y), pack2(v0.z, v0.w),
                                  pack2(v1.x, v1.y), pack2(v1.z, v1.w));
            } else sts128(ast0 + ao, 0, 0, 0, 0);
            if (h1) {
                const float* sc = aef + c + 8;
                float4 v2 = *reinterpret_cast<const float4*>(sc);
                float4 v3 = *reinterpret_cast<const float4*>(sc + 4);
                sts128(ast1 + ao, pack2(v2.x, v2.y), pack2(v2.z, v2.w),
                                  pack2(v3.x, v3.y), pack2(v3.z, v3.w));
            } else sts128(ast1 + ao, 0, 0, 0, 0);
        }
    };

    // prologue stage 0
    {
        produce_A(kbase, 0);
#pragma unroll
        for (int i = 0; i < 4; i++) {
            int kk = kbase + bko[i];
            if (kk + 8 <= kend) cp_async16_s(bst[i], bsrc[i] + kk);
            else                sts128(bst[i], 0, 0, 0, 0);
        }
        cp_async_commit();
        cp_async_wait0();
        __syncthreads();
    }

    int buf = 0;
#pragma unroll 1
    for (int s = 0; s < Q_NSTG; s++) {
        const bool nx = (s + 1) < Q_NSTG;
        if (nx) {
            const uint32_t ao = (uint32_t)(buf ^ 1) * Q_AB;
            const uint32_t bo = (uint32_t)(buf ^ 1) * Q_BB;
            int kb = kbase + (s + 1) * 64;
            produce_A(kb, ao);
#pragma unroll
            for (int i = 0; i < 4; i++) {
                int kk = kb + bko[i];
                if (kk + 8 <= kend) cp_async16_s(bst[i] + bo, bsrc[i] + kk);
                else                sts128(bst[i] + bo, 0, 0, 0, 0);
            }
            cp_async_commit();
        }

        const uint32_t Ab = (uint32_t)buf * Q_AB;
        const uint32_t Bb = (uint32_t)buf * Q_BB;
#pragma unroll
        for (int ks = 0; ks < 4; ks++) {
            uint32_t a0[4];
            const uint32_t au = (((uint32_t)(ks * 2 + akh)) * 16) ^ acx;
            ldsm_x4(a0, ac_base + Ab + au);
            const uint32_t bu = (((uint32_t)(ks * 2 + bkh)) * 16) ^ bcx;
#pragma unroll
            for (int ntp = 0; ntp < 4; ntp++) {
                uint32_t b[4];
                ldsm_x4(b, bc_base + Bb + ntp * 2048 + bu);
                mma_bf16(acc[2*ntp][0], acc[2*ntp][1], acc[2*ntp][2], acc[2*ntp][3],
                         a0[0], a0[1], a0[2], a0[3], b[0], b[1]);
                mma_bf16(acc[2*ntp+1][0], acc[2*ntp+1][1], acc[2*ntp+1][2], acc[2*ntp+1][3],
                         a0[0], a0[1], a0[2], a0[3], b[2], b[3]);
            }
        }

        if (nx) cp_async_wait0();
        __syncthreads();
        buf ^= 1;
    }

    float* part = g_part + (size_t)kz * 4 * BATCH * H;
#pragma unroll
    for (int nt = 0; nt < 8; nt++) {
        int col = nb * 128 + wn * 64 + nt * 8 + tig * 2;
        int rlo = vm0 + wm * 16 + g;
        int rhi = rlo + 8;
        part[(size_t)rlo * H + col]     = acc[nt][0];
        part[(size_t)rlo * H + col + 1] = acc[nt][1];
        part[(size_t)rhi * H + col]     = acc[nt][2];
        part[(size_t)rhi * H + col + 1] = acc[nt][3];
    }
}

// =============================================================================
// Kernel 5: [2048 x 256] @ W2[256 x 256] + b2, relu -> g_h2 (fp32 SIMT).
// A is produced inline: relu(sum_kz g_part + b1)  (rows 0..2047, src 0/1).
// =============================================================================
#define PSTRIDE ((size_t)4 * BATCH * H)

__global__ __launch_bounds__(256) void k_gemm2(
    const float* __restrict__ W2, const float* __restrict__ b2,
    const float* __restrict__ b1)
{
    const int BM = 32, BN = 128, KT = 32;
    __shared__ __align__(16) float As[KT][BM];
    __shared__ __align__(16) float Bs[KT][BN];

    int t  = threadIdx.x;
    int mb = blockIdx.x;
    int nb = blockIdx.y;
    int m0 = mb * BM;

    float acc[4][4];
#pragma unroll
    for (int i = 0; i < 4; i++)
#pragma unroll
        for (int j = 0; j < 4; j++) acc[i][j] = 0.f;

    int tr = t >> 5, tc = t & 31;
    int arow  = t >> 3;
    int akoff = (t & 7) << 2;
    const size_t rowoff = (size_t)(m0 + arow) * H;

    for (int k0 = 0; k0 < H; k0 += KT) {
        size_t o = rowoff + k0 + akoff;
        float4 p0 = *reinterpret_cast<const float4*>(&g_part[o]);
        float4 p1 = *reinterpret_cast<const float4*>(&g_part[PSTRIDE + o]);
        float4 p2 = *reinterpret_cast<const float4*>(&g_part[2 * PSTRIDE + o]);
        float4 p3 = *reinterpret_cast<const float4*>(&g_part[3 * PSTRIDE + o]);
        float4 bv = *reinterpret_cast<const float4*>(&b1[k0 + akoff]);
        float4 v;
        v.x = fmaxf(p0.x + p1.x + p2.x + p3.x + bv.x, 0.f);
        v.y = fmaxf(p0.y + p1.y + p2.y + p3.y + bv.y, 0.f);
        v.z = fmaxf(p0.z + p1.z + p2.z + p3.z + bv.z, 0.f);
        v.w = fmaxf(p0.w + p1.w + p2.w + p3.w + bv.w, 0.f);
        As[akoff + 0][arow] = v.x;
        As[akoff + 1][arow] = v.y;
        As[akoff + 2][arow] = v.z;
        As[akoff + 3][arow] = v.w;
#pragma unroll
        for (int i = 0; i < 16; i++) {
            int li  = i * 256 + t;
            int kk  = li >> 7;
            int col = li & 127;
            Bs[kk][col] = W2[(size_t)(k0 + kk) * H + nb * BN + col];
        }
        __syncthreads();
#pragma unroll
        for (int kk = 0; kk < KT; kk++) {
            float4 a = *reinterpret_cast<const float4*>(&As[kk][tr * 4]);
            float4 b = *reinterpret_cast<const float4*>(&Bs[kk][tc * 4]);
            float av[4] = {a.x, a.y, a.z, a.w};
            float bv2[4] = {b.x, b.y, b.z, b.w};
#pragma unroll
            for (int i = 0; i < 4; i++)
#pragma unroll
                for (int j = 0; j < 4; j++)
                    acc[i][j] = fmaf(av[i], bv2[j], acc[i][j]);
        }
        __syncthreads();
    }

#pragma unroll
    for (int i = 0; i < 4; i++) {
        int row = m0 + tr * 4 + i;
#pragma unroll
        for (int j = 0; j < 4; j++) {
            int col = nb * BN + tc * 4 + j;
            g_h2[(size_t)row * H + col] = fmaxf(acc[i][j] + b2[col], 0.f);
        }
    }
}

// =============================================================================
// Kernel 6: combine + LayerNorm + gate + concat output.
// Inline split-K reduce + bias + relu for rows 2048..4095 (src 2/3).
// =============================================================================
__global__ __launch_bounds__(256) void k_epilogue(
    const float* __restrict__ enc,
    const float* __restrict__ bd, const float* __restrict__ br,
    const float* __restrict__ lng, const float* __restrict__ lnb,
    const float* __restrict__ mgate, const float* __restrict__ cgate,
    float* __restrict__ out)
{
    int b = blockIdx.x;
    int t = threadIdx.x;

    float p1 = g_h2[(size_t)b * H + t];
    float p2 = g_h2[(size_t)(BATCH + b) * H + t];
    float gg = 1.f / (1.f + __expf(-cgate[t]));

    size_t o2 = ((size_t)2 * BATCH + b) * H + t;
    size_t o3 = ((size_t)3 * BATCH + b) * H + t;
    float d2 = g_part[o2] + g_part[PSTRIDE + o2] + g_part[2 * PSTRIDE + o2]
             + g_part[3 * PSTRIDE + o2];
    float d3 = g_part[o3] + g_part[PSTRIDE + o3] + g_part[2 * PSTRIDE + o3]
             + g_part[3 * PSTRIDE + o3];
    float lin2 = fmaxf(d2 + bd[t], 0.f);
    float lin3 = fmaxf(d3 + br[t], 0.f);

    float p = gg * p1 + (1.f - gg) * p2 + lin2 + lin3;

    float s1 = p, s2 = p * p;
#pragma unroll
    for (int off = 16; off > 0; off >>= 1) {
        s1 += __shfl_xor_sync(0xffffffffu, s1, off);
        s2 += __shfl_xor_sync(0xffffffffu, s2, off);
    }
    __shared__ float red[16];
    int wid = t >> 5, lane = t & 31;
    if (lane == 0) { red[wid] = s1; red[8 + wid] = s2; }
    __syncthreads();
    float mu = 0.f, ex2 = 0.f;
#pragma unroll
    for (int i = 0; i < 8; i++) { mu += red[i]; ex2 += red[8 + i]; }
    mu  *= (1.f / H);
    ex2 *= (1.f / H);
    float var = ex2 - mu * mu;

    float v  = (p - mu) * rsqrtf(var + 1e-5f) * lng[t] + lnb[t];
    float mg = 1.f / (1.f + __expf(-mgate[t]));
    out[(size_t)b * (D + H) + D + t] = mg * v;

    const float4* e4 = reinterpret_cast<const float4*>(enc + (size_t)b * D);
    float4* o4 = reinterpret_cast<float4*>(out + (size_t)b * (D + H));
    for (int j = t; j < D / 4; j += 256) o4[j] = e4[j];
}

// =============================================================================
extern "C" void kernel_launch(void* const* d_in, const int* in_sizes, int n_in,
                              void* d_out, int out_size)
{
    const float* enc  = (const float*)d_in[0];
    const int*   idx1 = (const int*)  d_in[1];
    const float* nw1  = (const float*)d_in[2];
    const int*   idx2 = (const int*)  d_in[3];
    const float* nw2  = (const float*)d_in[4];
    const float* sp   = (const float*)d_in[5];
    const float* un   = (const float*)d_in[6];
    const float* W1   = (const float*)d_in[7];
    const float* b1   = (const float*)d_in[8];
    const float* W2   = (const float*)d_in[9];
    const float* b2   = (const float*)d_in[10];
    const float* Wa1  = (const float*)d_in[11];
    const float* ba1  = (const float*)d_in[12];
    const float* Wa2  = (const float*)d_in[13];
    const float* ba2  = (const float*)d_in[14];
    const float* Wd   = (const float*)d_in[15];
    const float* bd   = (const float*)d_in[16];
    const float* Wr   = (const float*)d_in[17];
    const float* br   = (const float*)d_in[18];
    const float* lng  = (const float*)d_in[19];
    const float* lnb  = (const float*)d_in[20];
    const float* mg   = (const float*)d_in[21];
    const float* cg   = (const float*)d_in[22];
    float* out = (float*)d_out;

    cudaFuncSetAttribute(k_logits_fused, cudaFuncAttributeMaxDynamicSharedMemorySize, L_SMEM);
    cudaFuncSetAttribute(k_gemm4_v3,     cudaFuncAttributeMaxDynamicSharedMemorySize, Q_SMEM);

    k_cvt         <<<dim3(D / 32, H / 32, 4), dim3(32, 8)>>>(Wa1, W1, Wd, Wr);
    k_logits_fused<<<NROWS / L_BM, 1024, L_SMEM>>>(idx1, idx2, nw1, nw2, sp, un, ba1, Wa2, ba2);
    k_gemm4_v3    <<<dim3(64, 2, 4), 256, Q_SMEM>>>(enc);
    k_gemm2       <<<dim3(64, 2), 256>>>(W2, b2, b1);
    k_epilogue    <<<BATCH, 256>>>(enc, bd, br, lng, lnb, mg, cg, out);
}

// round 16
// speedup vs baseline: 1.1265x; 1.1265x over previous
#include <cuda_runtime.h>
#include <cuda_bf16.h>
#include <math.h>
#include <stdint.h>

#define BATCH 1024
#define KNN   16
#define H     256
#define G     2000
#define D     4000          // 2*G
#define NROWS (2*BATCH*KNN) // 32768

typedef __nv_bfloat16 bf16;

// ---------------- scratch (static device arrays; no allocation) --------------
__device__ bf16  g_aggb[(size_t)2 * BATCH * D];      // bf16 agg, 16MB
__device__ float g_part[(size_t)4 * 4 * BATCH * H]; // split-K partials, 16MB
__device__ float g_h2[(size_t)2 * BATCH * H];
__device__ bf16  g_wt[4][(size_t)H * D];             // W^T bf16: [n][k], 8MB

// ----------------------------- PTX helpers ----------------------------------
__device__ __forceinline__ uint32_t smem_u32(const void* p) {
    uint32_t a;
    asm("{ .reg .u64 tmp; cvta.to.shared.u64 tmp, %1; cvt.u32.u64 %0, tmp; }"
        : "=r"(a) : "l"(p));
    return a;
}

__device__ __forceinline__ void mma_bf16(float& c0, float& c1, float& c2, float& c3,
                                         uint32_t a0, uint32_t a1, uint32_t a2, uint32_t a3,
                                         uint32_t b0, uint32_t b1) {
    asm volatile(
        "mma.sync.aligned.m16n8k16.row.col.f32.bf16.bf16.f32 "
        "{%0,%1,%2,%3}, {%4,%5,%6,%7}, {%8,%9}, {%0,%1,%2,%3};\n"
        : "+f"(c0), "+f"(c1), "+f"(c2), "+f"(c3)
        : "r"(a0), "r"(a1), "r"(a2), "r"(a3), "r"(b0), "r"(b1));
}

__device__ __forceinline__ void ldsm_x4(uint32_t* r, uint32_t addr) {
    asm volatile("ldmatrix.sync.aligned.m8n8.x4.shared.b16 {%0,%1,%2,%3}, [%4];"
                 : "=r"(r[0]), "=r"(r[1]), "=r"(r[2]), "=r"(r[3]) : "r"(addr));
}

__device__ __forceinline__ void sts128(uint32_t addr, uint32_t a, uint32_t b,
                                       uint32_t c, uint32_t d) {
    asm volatile("st.shared.v4.b32 [%0], {%1,%2,%3,%4};"
                 :: "r"(addr), "r"(a), "r"(b), "r"(c), "r"(d));
}

__device__ __forceinline__ void cp_async16_s(uint32_t saddr, const void* gsrc) {
    asm volatile("cp.async.ca.shared.global [%0], [%1], 16;\n" :: "r"(saddr), "l"(gsrc));
}
__device__ __forceinline__ void cp_async_commit() { asm volatile("cp.async.commit_group;\n"); }
__device__ __forceinline__ void cp_async_wait0()  { asm volatile("cp.async.wait_group 0;\n"); }

__device__ __forceinline__ uint32_t pack2(float x, float y) {
    __nv_bfloat162 h = __floats2bfloat162_rn(x, y);
    return *reinterpret_cast<uint32_t*>(&h);
}

__device__ __forceinline__ float tanh_fast(float x) {
    float e = __expf(2.f * x);
    return 1.f - __fdividef(2.f, e + 1.f);
}

// =============================================================================
// Kernel 0: convert + transpose weights to bf16 W^T[n][k] (k contiguous).
// =============================================================================
__global__ void k_cvt(const float* __restrict__ Wa1, const float* __restrict__ W1,
                      const float* __restrict__ Wd, const float* __restrict__ Wr)
{
    __shared__ float tile[32][33];
    const float* src = (blockIdx.z == 0) ? Wa1 : (blockIdx.z == 1) ? W1
                     : (blockIdx.z == 2) ? Wd : Wr;
    bf16* dst = g_wt[blockIdx.z];
    int k0 = blockIdx.x * 32, n0 = blockIdx.y * 32;
    int tx = threadIdx.x, ty = threadIdx.y;
#pragma unroll
    for (int i = 0; i < 4; i++)
        tile[ty + 8 * i][tx] = src[(size_t)(k0 + ty + 8 * i) * H + n0 + tx];
    __syncthreads();
#pragma unroll
    for (int i = 0; i < 4; i++)
        dst[(size_t)(n0 + ty + 8 * i) * D + k0 + tx] = __float2bfloat16(tile[tx][ty + 8 * i]);
}

// =============================================================================
// Kernel 1 (bf16 mma + ldmatrix): attention logits + FUSED weights/aggregation.
// Block = 128 rows = 8 complete (graph,b) groups. After the logits epilogue the
// block computes the softmax-folded weights and the weighted gather-aggregate
// for its 8 groups (bf16 out to g_aggb). Round-11 mainloop, unchanged.
// =============================================================================
#define L_BM 128
#define L_NSTG 63
#define L_AB 16384
#define L_BB 32768
#define L_SMEM (2*L_AB + 2*L_BB)

__global__ __launch_bounds__(512, 1) void k_logits_fused(
    const int* __restrict__ idx1, const int* __restrict__ idx2,
    const float* __restrict__ nw1, const float* __restrict__ nw2,
    const float* __restrict__ sp, const float* __restrict__ un,
    const float* __restrict__ ba1, const float* __restrict__ Wa2,
    const float* __restrict__ ba2)
{
    extern __shared__ __align__(1024) char sm[];
    __shared__ int   rid[L_BM];
    __shared__ float psum[4 * L_BM];
    __shared__ float s_ba1[256], s_wa2[256];
    __shared__ float s_lgt[L_BM];
    __shared__ float s_w[L_BM];

    const int t    = threadIdx.x;
    const int lane = t & 31;
    const int wid  = t >> 5;
    const int wm   = wid & 3;
    const int wn   = wid >> 2;
    const int g    = lane >> 2;
    const int tig  = lane & 3;
    const int row0 = blockIdx.x * L_BM;
    const int gb0  = blockIdx.x * 8;        // first (graph,b) group of this block
    const uint32_t smb = smem_u32(sm);

    if (t < L_BM) {
        int r = row0 + t;
        rid[t] = (r < BATCH * KNN) ? idx1[r] : idx2[r - BATCH * KNN];
    }
    if (t < 256) { s_ba1[t] = ba1[t]; s_wa2[t] = Wa2[t]; }
    __syncthreads();

    const int arow = t >> 2;
    const int agrp = t & 3;
    const size_t abase = (size_t)rid[arow] * G;
    const uint32_t axor = (uint32_t)(arow & 7) << 4;
    const uint32_t ast0 = smb + arow * 128 + (((uint32_t)agrp * 32) ^ axor);
    const uint32_t ast1 = smb + arow * 128 + (((uint32_t)agrp * 32 + 16) ^ axor);

    uint32_t bst[4]; const bf16* bsrc[4]; int bko[4];
#pragma unroll
    for (int i = 0; i < 4; i++) {
        int p = t + i * 512;
        int br = p >> 3, bc = p & 7;
        bst[i]  = smb + 2 * L_AB + br * 128 + (((uint32_t)bc * 16) ^ ((uint32_t)(br & 7) << 4));
        bsrc[i] = g_wt[0] + (size_t)br * D;
        bko[i]  = bc * 8;
    }

    const int ar_lo = (lane & 7) + ((lane >> 3) & 1) * 8;
    const int akh   = (lane >> 4) & 1;
    const uint32_t ac_base = smb + (wm * 32 + ar_lo) * 128;
    const uint32_t acx = (uint32_t)(ar_lo & 7) << 4;
    const int nr_lo = (lane & 7) + ((lane >> 4) & 1) * 8;
    const int bkh   = (lane >> 3) & 1;
    const uint32_t bc_base = smb + 2 * L_AB + (wn * 64 + nr_lo) * 128;
    const uint32_t bcx = (uint32_t)(nr_lo & 7) << 4;

    float acc[2][8][4];
#pragma unroll
    for (int mt = 0; mt < 2; mt++)
#pragma unroll
        for (int nt = 0; nt < 8; nt++)
#pragma unroll
            for (int j = 0; j < 4; j++) acc[mt][nt][j] = 0.f;

    // ---- prologue: stage 0 ----
    {
        const float* s0 = sp + abase + agrp * 16;
        float4 v0 = *reinterpret_cast<const float4*>(s0);
        float4 v1 = *reinterpret_cast<const float4*>(s0 + 4);
        float4 v2 = *reinterpret_cast<const float4*>(s0 + 8);
        float4 v3 = *reinterpret_cast<const float4*>(s0 + 12);
        sts128(ast0, pack2(__logf(v0.x + 0.01f), __logf(v0.y + 0.01f)),
                     pack2(__logf(v0.z + 0.01f), __logf(v0.w + 0.01f)),
                     pack2(__logf(v1.x + 0.01f), __logf(v1.y + 0.01f)),
                     pack2(__logf(v1.z + 0.01f), __logf(v1.w + 0.01f)));
        sts128(ast1, pack2(__logf(v2.x + 0.01f), __logf(v2.y + 0.01f)),
                     pack2(__logf(v2.z + 0.01f), __logf(v2.w + 0.01f)),
                     pack2(__logf(v3.x + 0.01f), __logf(v3.y + 0.01f)),
                     pack2(__logf(v3.z + 0.01f), __logf(v3.w + 0.01f)));
#pragma unroll
        for (int i = 0; i < 4; i++)
            cp_async16_s(bst[i], bsrc[i] + bko[i]);
        cp_async_commit();
        cp_async_wait0();
        __syncthreads();
    }

    int buf = 0;
#pragma unroll 1
    for (int s = 0; s < L_NSTG; s++) {
        const bool nx = (s + 1) < L_NSTG;
        float4 v0, v1, v2, v3;
        bool vn = false;
        if (nx) {
            int c = (s + 1) * 64 + agrp * 16;
            vn = (c < D);
            if (vn) {
                const float* sc = (c < G) ? (sp + abase + c) : (un + abase + (c - G));
                v0 = *reinterpret_cast<const float4*>(sc);
                v1 = *reinterpret_cast<const float4*>(sc + 4);
                v2 = *reinterpret_cast<const float4*>(sc + 8);
                v3 = *reinterpret_cast<const float4*>(sc + 12);
            }
            const uint32_t bo = (uint32_t)(buf ^ 1) * L_BB;
#pragma unroll
            for (int i = 0; i < 4; i++) {
                int kk = (s + 1) * 64 + bko[i];
                if (kk + 8 <= D) cp_async16_s(bst[i] + bo, bsrc[i] + kk);
                else             sts128(bst[i] + bo, 0, 0, 0, 0);
            }
            cp_async_commit();
        }

        const uint32_t Ab = (uint32_t)buf * L_AB;
        const uint32_t Bb = (uint32_t)buf * L_BB;
#pragma unroll
        for (int ks = 0; ks < 4; ks++) {
            uint32_t a0[4], a1[4];
            const uint32_t au = (((uint32_t)(ks * 2 + akh)) * 16) ^ acx;
            ldsm_x4(a0, ac_base + Ab + au);
            ldsm_x4(a1, ac_base + Ab + 2048 + au);
            const uint32_t bu = (((uint32_t)(ks * 2 + bkh)) * 16) ^ bcx;
#pragma unroll
            for (int ntp = 0; ntp < 4; ntp++) {
                uint32_t b[4];
                ldsm_x4(b, bc_base + Bb + ntp * 2048 + bu);
                mma_bf16(acc[0][2*ntp][0], acc[0][2*ntp][1], acc[0][2*ntp][2], acc[0][2*ntp][3],
                         a0[0], a0[1], a0[2], a0[3], b[0], b[1]);
                mma_bf16(acc[0][2*ntp+1][0], acc[0][2*ntp+1][1], acc[0][2*ntp+1][2], acc[0][2*ntp+1][3],
                         a0[0], a0[1], a0[2], a0[3], b[2], b[3]);
                mma_bf16(acc[1][2*ntp][0], acc[1][2*ntp][1], acc[1][2*ntp][2], acc[1][2*ntp][3],
                         a1[0], a1[1], a1[2], a1[3], b[0], b[1]);
                mma_bf16(acc[1][2*ntp+1][0], acc[1][2*ntp+1][1], acc[1][2*ntp+1][2], acc[1][2*ntp+1][3],
                         a1[0], a1[1], a1[2], a1[3], b[2], b[3]);
            }
        }

        if (nx) {
            const uint32_t ao = (uint32_t)(buf ^ 1) * L_AB;
            if (vn) {
                sts128(ast0 + ao, pack2(__logf(v0.x + 0.01f), __logf(v0.y + 0.01f)),
                                  pack2(__logf(v0.z + 0.01f), __logf(v0.w + 0.01f)),
                                  pack2(__logf(v1.x + 0.01f), __logf(v1.y + 0.01f)),
                                  pack2(__logf(v1.z + 0.01f), __logf(v1.w + 0.01f)));
                sts128(ast1 + ao, pack2(__logf(v2.x + 0.01f), __logf(v2.y + 0.01f)),
                                  pack2(__logf(v2.z + 0.01f), __logf(v2.w + 0.01f)),
                                  pack2(__logf(v3.x + 0.01f), __logf(v3.y + 0.01f)),
                                  pack2(__logf(v3.z + 0.01f), __logf(v3.w + 0.01f)));
            } else {
                sts128(ast0 + ao, 0, 0, 0, 0);
                sts128(ast1 + ao, 0, 0, 0, 0);
            }
        }
        cp_async_wait0();
        __syncthreads();
        buf ^= 1;
    }

    // ---------- logits epilogue: fast tanh + dot(Wa2), hierarchical reduce ----
    float bb[8][2], ww[8][2];
#pragma unroll
    for (int nt = 0; nt < 8; nt++) {
        int col = wn * 64 + nt * 8 + tig * 2;
        bb[nt][0] = s_ba1[col];  bb[nt][1] = s_ba1[col + 1];
        ww[nt][0] = s_wa2[col];  ww[nt][1] = s_wa2[col + 1];
    }
#pragma unroll
    for (int mt = 0; mt < 2; mt++) {
        float slo = 0.f, shi = 0.f;
#pragma unroll
        for (int nt = 0; nt < 8; nt++) {
            slo += tanh_fast(acc[mt][nt][0] + bb[nt][0]) * ww[nt][0];
            slo += tanh_fast(acc[mt][nt][1] + bb[nt][1]) * ww[nt][1];
            shi += tanh_fast(acc[mt][nt][2] + bb[nt][0]) * ww[nt][0];
            shi += tanh_fast(acc[mt][nt][3] + bb[nt][1]) * ww[nt][1];
        }
        slo += __shfl_xor_sync(0xffffffffu, slo, 1);
        slo += __shfl_xor_sync(0xffffffffu, slo, 2);
        shi += __shfl_xor_sync(0xffffffffu, shi, 1);
        shi += __shfl_xor_sync(0xffffffffu, shi, 2);
        if (tig == 0) {
            psum[wn * L_BM + wm * 32 + mt * 16 + g]     = slo;
            psum[wn * L_BM + wm * 32 + mt * 16 + g + 8] = shi;
        }
    }
    __syncthreads();
    if (t < L_BM) {
        float s = psum[t] + psum[L_BM + t] + psum[2 * L_BM + t] + psum[3 * L_BM + t];
        s_lgt[t] = s + __ldg(&ba2[0]);
    }
    __syncthreads();

    // ---------- fused weights: softmax over 16 logits + nw fold, per group ----
    if (t < 8) {
        int gb = gb0 + t;
        const float* nwp = (gb < BATCH) ? (nw1 + (size_t)gb * KNN)
                                        : (nw2 + (size_t)(gb - BATCH) * KNN);
        float l[KNN];
        float m = -1e30f;
#pragma unroll
        for (int k = 0; k < KNN; k++) { l[k] = s_lgt[t * KNN + k]; m = fmaxf(m, l[k]); }
        float ssum = 0.f;
#pragma unroll
        for (int k = 0; k < KNN; k++) { l[k] = __expf(l[k] - m); ssum += l[k]; }
        float inv_s = 1.f / ssum;
        float tsum = 0.f;
#pragma unroll
        for (int k = 0; k < KNN; k++) { l[k] = nwp[k] * l[k] * inv_s; tsum += l[k]; }
        float inv = 1.f / (tsum + 1e-12f);
#pragma unroll
        for (int k = 0; k < KNN; k++) s_w[t * KNN + k] = l[k] * inv;
    }
    __syncthreads();

    // ---------- fused aggregation: 8 groups x 500 col-chunks of 8 ----
#pragma unroll 1
    for (int task = t; task < 4000; task += 512) {
        int grp = task / 500;
        int ch  = task - grp * 500;
        int c   = ch * 8;
        const float* base = (c < G) ? sp : un;
        int cc = (c < G) ? c : c - G;
        const int*   idp = rid + grp * KNN;
        const float* wp  = s_w + grp * KNN;
        float a[8];
#pragma unroll
        for (int j = 0; j < 8; j++) a[j] = 0.f;
#pragma unroll
        for (int k = 0; k < KNN; k++) {
            const float* rp = base + (size_t)idp[k] * G + cc;
            float4 v0 = *reinterpret_cast<const float4*>(rp);
            float4 v1 = *reinterpret_cast<const float4*>(rp + 4);
            float wk = wp[k];
            a[0] = fmaf(wk, __logf(v0.x + 0.01f), a[0]);
            a[1] = fmaf(wk, __logf(v0.y + 0.01f), a[1]);
            a[2] = fmaf(wk, __logf(v0.z + 0.01f), a[2]);
            a[3] = fmaf(wk, __logf(v0.w + 0.01f), a[3]);
            a[4] = fmaf(wk, __logf(v1.x + 0.01f), a[4]);
            a[5] = fmaf(wk, __logf(v1.y + 0.01f), a[5]);
            a[6] = fmaf(wk, __logf(v1.z + 0.01f), a[6]);
            a[7] = fmaf(wk, __logf(v1.w + 0.01f), a[7]);
        }
        uint4 pk;
        pk.x = pack2(a[0], a[1]); pk.y = pack2(a[2], a[3]);
        pk.z = pack2(a[4], a[5]); pk.w = pack2(a[6], a[7]);
        *reinterpret_cast<uint4*>(&g_aggb[(size_t)(gb0 + grp) * D + c]) = pk;
    }
}

// =============================================================================
// Kernel 4 (bf16 mma + ldmatrix + split-K x4): four fused GEMMs, virtual M=4096.
// Block 64x128xK1000, grid (64, 2, 4) = 512 CTAs. Partials -> g_part.
// =============================================================================
#define Q_AB 8192
#define Q_BB 16384
#define Q_SMEM (2*Q_AB + 2*Q_BB)
#define Q_KSPLIT 1000
#define Q_NSTG 16            // ceil(1000/64)

__global__ __launch_bounds__(256, 3) void k_gemm4_v3(
    const float* __restrict__ enc)
{
    extern __shared__ __align__(1024) char sm[];

    const int t    = threadIdx.x;
    const int lane = t & 31;
    const int wid  = t >> 5;
    const int wm   = wid & 3;
    const int wn   = wid >> 2;
    const int g    = lane >> 2;
    const int tig  = lane & 3;
    const int nb   = blockIdx.y;
    const int vm0  = blockIdx.x * 64;
    const int src  = vm0 >> 10;
    const int kz   = blockIdx.z;
    const int kbase = kz * Q_KSPLIT;
    const int kend  = kbase + Q_KSPLIT;
    const uint32_t smb = smem_u32(sm);

    const bf16* WT = (src < 2) ? g_wt[1] : (src == 2 ? g_wt[2] : g_wt[3]);

    const int arow = t >> 2;
    const int agrp = t & 3;
    const int brow = (vm0 & 1023) + arow;
    const bf16*  abf = nullptr;
    const float* aef = nullptr;
    if      (src == 0) abf = g_aggb + (size_t)brow * D;
    else if (src == 1) abf = g_aggb + (size_t)(BATCH + brow) * D;
    else if (src == 2) { abf = g_aggb + (size_t)brow * D; aef = enc + (size_t)brow * D; }
    else               aef = enc + (size_t)brow * D;

    const uint32_t axor = (uint32_t)(arow & 7) << 4;
    const uint32_t ast0 = smb + arow * 128 + (((uint32_t)agrp * 32) ^ axor);
    const uint32_t ast1 = smb + arow * 128 + (((uint32_t)agrp * 32 + 16) ^ axor);

    uint32_t bst[4]; const bf16* bsrc[4]; int bko[4];
#pragma unroll
    for (int i = 0; i < 4; i++) {
        int p = t + i * 256;
        int brr = p >> 3, bc = p & 7;
        bst[i]  = smb + 2 * Q_AB + brr * 128 + (((uint32_t)bc * 16) ^ ((uint32_t)(brr & 7) << 4));
        bsrc[i] = WT + (size_t)(nb * 128 + brr) * D;
        bko[i]  = bc * 8;
    }

    const int ar_lo = (lane & 7) + ((lane >> 3) & 1) * 8;
    const int akh   = (lane >> 4) & 1;
    const uint32_t ac_base = smb + (wm * 16 + ar_lo) * 128;
    const uint32_t acx = (uint32_t)(ar_lo & 7) << 4;
    const int nr_lo = (lane & 7) + ((lane >> 4) & 1) * 8;
    const int bkh   = (lane >> 3) & 1;
    const uint32_t bc_base = smb + 2 * Q_AB + (wn * 64 + nr_lo) * 128;
    const uint32_t bcx = (uint32_t)(nr_lo & 7) << 4;

    float acc[8][4];
#pragma unroll
    for (int nt = 0; nt < 8; nt++)
#pragma unroll
        for (int j = 0; j < 4; j++) acc[nt][j] = 0.f;

    auto produce_A = [&](int kb0, uint32_t ao) {
        int c = kb0 + agrp * 16;
        bool h0 = (c + 8 <= kend), h1 = (c + 16 <= kend);
        if (src < 2) {
            if (h0) cp_async16_s(ast0 + ao, abf + c);
            else    sts128(ast0 + ao, 0, 0, 0, 0);
            if (h1) cp_async16_s(ast1 + ao, abf + c + 8);
            else    sts128(ast1 + ao, 0, 0, 0, 0);
        } else if (src == 2) {
            if (h0) {
                uint4 ab0 = *reinterpret_cast<const uint4*>(abf + c);
                float4 e0 = *reinterpret_cast<const float4*>(aef + c);
                float4 e1 = *reinterpret_cast<const float4*>(aef + c + 4);
                __nv_bfloat162* al = reinterpret_cast<__nv_bfloat162*>(&ab0);
                float2 f0 = __bfloat1622float2(al[0]);
                float2 f1 = __bfloat1622float2(al[1]);
                float2 f2 = __bfloat1622float2(al[2]);
                float2 f3 = __bfloat1622float2(al[3]);
                sts128(ast0 + ao,
                       pack2(f0.x - e0.x, f0.y - e0.y), pack2(f1.x - e0.z, f1.y - e0.w),
                       pack2(f2.x - e1.x, f2.y - e1.y), pack2(f3.x - e1.z, f3.y - e1.w));
            } else sts128(ast0 + ao, 0, 0, 0, 0);
            if (h1) {
                uint4 ab1 = *reinterpret_cast<const uint4*>(abf + c + 8);
                float4 e2 = *reinterpret_cast<const float4*>(aef + c + 8);
                float4 e3 = *reinterpret_cast<const float4*>(aef + c + 12);
                __nv_bfloat162* ah = reinterpret_cast<__nv_bfloat162*>(&ab1);
                float2 f4 = __bfloat1622float2(ah[0]);
                float2 f5 = __bfloat1622float2(ah[1]);
                float2 f6 = __bfloat1622float2(ah[2]);
                float2 f7 = __bfloat1622float2(ah[3]);
                sts128(ast1 + ao,
                       pack2(f4.x - e2.x, f4.y - e2.y), pack2(f5.x - e2.z, f5.y - e2.w),
                       pack2(f6.x - e3.x, f6.y - e3.y), pack2(f7.x - e3.z, f7.y - e3.w));
            } else sts128(ast1 + ao, 0, 0, 0, 0);
        } else {
            if (h0) {
                const float* sc = aef + c;
                float4 v0 = *reinterpret_cast<const float4*>(sc);
                float4 v1 = *reinterpret_cast<const float4*>(sc + 4);
                sts128(ast0 + ao, pack2(v0.x, v0.y), pack2(v0.z, v0.w),
                                  pack2(v1.x, v1.y), pack2(v1.z, v1.w));
            } else sts128(ast0 + ao, 0, 0, 0, 0);
            if (h1) {
                const float* sc = aef + c + 8;
                float4 v2 = *reinterpret_cast<const float4*>(sc);
                float4 v3 = *reinterpret_cast<const float4*>(sc + 4);
                sts128(ast1 + ao, pack2(v2.x, v2.y), pack2(v2.z, v2.w),
                                  pack2(v3.x, v3.y), pack2(v3.z, v3.w));
            } else sts128(ast1 + ao, 0, 0, 0, 0);
        }
    };

    // prologue stage 0
    {
        produce_A(kbase, 0);
#pragma unroll
        for (int i = 0; i < 4; i++) {
            int kk = kbase + bko[i];
            if (kk + 8 <= kend) cp_async16_s(bst[i], bsrc[i] + kk);
            else                sts128(bst[i], 0, 0, 0, 0);
        }
        cp_async_commit();
        cp_async_wait0();
        __syncthreads();
    }

    int buf = 0;
#pragma unroll 1
    for (int s = 0; s < Q_NSTG; s++) {
        const bool nx = (s + 1) < Q_NSTG;
        if (nx) {
            const uint32_t ao = (uint32_t)(buf ^ 1) * Q_AB;
            const uint32_t bo = (uint32_t)(buf ^ 1) * Q_BB;
            int kb = kbase + (s + 1) * 64;
            produce_A(kb, ao);
#pragma unroll
            for (int i = 0; i < 4; i++) {
                int kk = kb + bko[i];
                if (kk + 8 <= kend) cp_async16_s(bst[i] + bo, bsrc[i] + kk);
                else                sts128(bst[i] + bo, 0, 0, 0, 0);
            }
            cp_async_commit();
        }

        const uint32_t Ab = (uint32_t)buf * Q_AB;
        const uint32_t Bb = (uint32_t)buf * Q_BB;
#pragma unroll
        for (int ks = 0; ks < 4; ks++) {
            uint32_t a0[4];
            const uint32_t au = (((uint32_t)(ks * 2 + akh)) * 16) ^ acx;
            ldsm_x4(a0, ac_base + Ab + au);
            const uint32_t bu = (((uint32_t)(ks * 2 + bkh)) * 16) ^ bcx;
#pragma unroll
            for (int ntp = 0; ntp < 4; ntp++) {
                uint32_t b[4];
                ldsm_x4(b, bc_base + Bb + ntp * 2048 + bu);
                mma_bf16(acc[2*ntp][0], acc[2*ntp][1], acc[2*ntp][2], acc[2*ntp][3],
                         a0[0], a0[1], a0[2], a0[3], b[0], b[1]);
                mma_bf16(acc[2*ntp+1][0], acc[2*ntp+1][1], acc[2*ntp+1][2], acc[2*ntp+1][3],
                         a0[0], a0[1], a0[2], a0[3], b[2], b[3]);
            }
        }

        if (nx) cp_async_wait0();
        __syncthreads();
        buf ^= 1;
    }

    float* part = g_part + (size_t)kz * 4 * BATCH * H;
#pragma unroll
    for (int nt = 0; nt < 8; nt++) {
        int col = nb * 128 + wn * 64 + nt * 8 + tig * 2;
        int rlo = vm0 + wm * 16 + g;
        int rhi = rlo + 8;
        part[(size_t)rlo * H + col]     = acc[nt][0];
        part[(size_t)rlo * H + col + 1] = acc[nt][1];
        part[(size_t)rhi * H + col]     = acc[nt][2];
        part[(size_t)rhi * H + col + 1] = acc[nt][3];
    }
}

// =============================================================================
// Kernel 5: [2048 x 256] @ W2[256 x 256] + b2, relu -> g_h2 (fp32 SIMT).
// A is produced inline: relu(sum_kz g_part + b1)  (rows 0..2047, src 0/1).
// =============================================================================
#define PSTRIDE ((size_t)4 * BATCH * H)

__global__ __launch_bounds__(256) void k_gemm2(
    const float* __restrict__ W2, const float* __restrict__ b2,
    const float* __restrict__ b1)
{
    const int BM = 32, BN = 128, KT = 32;
    __shared__ __align__(16) float As[KT][BM];
    __shared__ __align__(16) float Bs[KT][BN];

    int t  = threadIdx.x;
    int mb = blockIdx.x;
    int nb = blockIdx.y;
    int m0 = mb * BM;

    float acc[4][4];
#pragma unroll
    for (int i = 0; i < 4; i++)
#pragma unroll
        for (int j = 0; j < 4; j++) acc[i][j] = 0.f;

    int tr = t >> 5, tc = t & 31;
    int arow  = t >> 3;
    int akoff = (t & 7) << 2;
    const size_t rowoff = (size_t)(m0 + arow) * H;

    for (int k0 = 0; k0 < H; k0 += KT) {
        size_t o = rowoff + k0 + akoff;
        float4 p0 = *reinterpret_cast<const float4*>(&g_part[o]);
        float4 p1 = *reinterpret_cast<const float4*>(&g_part[PSTRIDE + o]);
        float4 p2 = *reinterpret_cast<const float4*>(&g_part[2 * PSTRIDE + o]);
        float4 p3 = *reinterpret_cast<const float4*>(&g_part[3 * PSTRIDE + o]);
        float4 bv = *reinterpret_cast<const float4*>(&b1[k0 + akoff]);
        float4 v;
        v.x = fmaxf(p0.x + p1.x + p2.x + p3.x + bv.x, 0.f);
        v.y = fmaxf(p0.y + p1.y + p2.y + p3.y + bv.y, 0.f);
        v.z = fmaxf(p0.z + p1.z + p2.z + p3.z + bv.z, 0.f);
        v.w = fmaxf(p0.w + p1.w + p2.w + p3.w + bv.w, 0.f);
        As[akoff + 0][arow] = v.x;
        As[akoff + 1][arow] = v.y;
        As[akoff + 2][arow] = v.z;
        As[akoff + 3][arow] = v.w;
#pragma unroll
        for (int i = 0; i < 16; i++) {
            int li  = i * 256 + t;
            int kk  = li >> 7;
            int col = li & 127;
            Bs[kk][col] = W2[(size_t)(k0 + kk) * H + nb * BN + col];
        }
        __syncthreads();
#pragma unroll
        for (int kk = 0; kk < KT; kk++) {
            float4 a = *reinterpret_cast<const float4*>(&As[kk][tr * 4]);
            float4 b = *reinterpret_cast<const float4*>(&Bs[kk][tc * 4]);
            float av[4] = {a.x, a.y, a.z, a.w};
            float bv2[4] = {b.x, b.y, b.z, b.w};
#pragma unroll
            for (int i = 0; i < 4; i++)
#pragma unroll
                for (int j = 0; j < 4; j++)
                    acc[i][j] = fmaf(av[i], bv2[j], acc[i][j]);
        }
        __syncthreads();
    }

#pragma unroll
    for (int i = 0; i < 4; i++) {
        int row = m0 + tr * 4 + i;
#pragma unroll
        for (int j = 0; j < 4; j++) {
            int col = nb * BN + tc * 4 + j;
            g_h2[(size_t)row * H + col] = fmaxf(acc[i][j] + b2[col], 0.f);
        }
    }
}

// =============================================================================
// Kernel 6: combine + LayerNorm + gate + concat output.
// Inline split-K reduce + bias + relu for rows 2048..4095 (src 2/3).
// =============================================================================
__global__ __launch_bounds__(256) void k_epilogue(
    const float* __restrict__ enc,
    const float* __restrict__ bd, const float* __restrict__ br,
    const float* __restrict__ lng, const float* __restrict__ lnb,
    const float* __restrict__ mgate, const float* __restrict__ cgate,
    float* __restrict__ out)
{
    int b = blockIdx.x;
    int t = threadIdx.x;

    float p1 = g_h2[(size_t)b * H + t];
    float p2 = g_h2[(size_t)(BATCH + b) * H + t];
    float gg = 1.f / (1.f + __expf(-cgate[t]));

    size_t o2 = ((size_t)2 * BATCH + b) * H + t;
    size_t o3 = ((size_t)3 * BATCH + b) * H + t;
    float d2 = g_part[o2] + g_part[PSTRIDE + o2] + g_part[2 * PSTRIDE + o2]
             + g_part[3 * PSTRIDE + o2];
    float d3 = g_part[o3] + g_part[PSTRIDE + o3] + g_part[2 * PSTRIDE + o3]
             + g_part[3 * PSTRIDE + o3];
    float lin2 = fmaxf(d2 + bd[t], 0.f);
    float lin3 = fmaxf(d3 + br[t], 0.f);

    float p = gg * p1 + (1.f - gg) * p2 + lin2 + lin3;

    float s1 = p, s2 = p * p;
#pragma unroll
    for (int off = 16; off > 0; off >>= 1) {
        s1 += __shfl_xor_sync(0xffffffffu, s1, off);
        s2 += __shfl_xor_sync(0xffffffffu, s2, off);
    }
    __shared__ float red[16];
    int wid = t >> 5, lane = t & 31;
    if (lane == 0) { red[wid] = s1; red[8 + wid] = s2; }
    __syncthreads();
    float mu = 0.f, ex2 = 0.f;
#pragma unroll
    for (int i = 0; i < 8; i++) { mu += red[i]; ex2 += red[8 + i]; }
    mu  *= (1.f / H);
    ex2 *= (1.f / H);
    float var = ex2 - mu * mu;

    float v  = (p - mu) * rsqrtf(var + 1e-5f) * lng[t] + lnb[t];
    float mg = 1.f / (1.f + __expf(-mgate[t]));
    out[(size_t)b * (D + H) + D + t] = mg * v;

    const float4* e4 = reinterpret_cast<const float4*>(enc + (size_t)b * D);
    float4* o4 = reinterpret_cast<float4*>(out + (size_t)b * (D + H));
    for (int j = t; j < D / 4; j += 256) o4[j] = e4[j];
}

// =============================================================================
extern "C" void kernel_launch(void* const* d_in, const int* in_sizes, int n_in,
                              void* d_out, int out_size)
{
    const float* enc  = (const float*)d_in[0];
    const int*   idx1 = (const int*)  d_in[1];
    const float* nw1  = (const float*)d_in[2];
    const int*   idx2 = (const int*)  d_in[3];
    const float* nw2  = (const float*)d_in[4];
    const float* sp   = (const float*)d_in[5];
    const float* un   = (const float*)d_in[6];
    const float* W1   = (const float*)d_in[7];
    const float* b1   = (const float*)d_in[8];
    const float* W2   = (const float*)d_in[9];
    const float* b2   = (const float*)d_in[10];
    const float* Wa1  = (const float*)d_in[11];
    const float* ba1  = (const float*)d_in[12];
    const float* Wa2  = (const float*)d_in[13];
    const float* ba2  = (const float*)d_in[14];
    const float* Wd   = (const float*)d_in[15];
    const float* bd   = (const float*)d_in[16];
    const float* Wr   = (const float*)d_in[17];
    const float* br   = (const float*)d_in[18];
    const float* lng  = (const float*)d_in[19];
    const float* lnb  = (const float*)d_in[20];
    const float* mg   = (const float*)d_in[21];
    const float* cg   = (const float*)d_in[22];
    float* out = (float*)d_out;

    cudaFuncSetAttribute(k_logits_fused, cudaFuncAttributeMaxDynamicSharedMemorySize, L_SMEM);
    cudaFuncSetAttribute(k_gemm4_v3,     cudaFuncAttributeMaxDynamicSharedMemorySize, Q_SMEM);

    k_cvt         <<<dim3(D / 32, H / 32, 4), dim3(32, 8)>>>(Wa1, W1, Wd, Wr);
    k_logits_fused<<<NROWS / L_BM, 512, L_SMEM>>>(idx1, idx2, nw1, nw2, sp, un, ba1, Wa2, ba2);
    k_gemm4_v3    <<<dim3(64, 2, 4), 256, Q_SMEM>>>(enc);
    k_gemm2       <<<dim3(64, 2), 256>>>(W2, b2, b1);
    k_epilogue    <<<BATCH, 256>>>(enc, bd, br, lng, lnb, mg, cg, out);
}